// round 7
// baseline (speedup 1.0000x reference)
#include <cuda_runtime.h>

#define BATCH 8
#define H 128
#define W 128
#define HW (H*W)

// ---------------- scratch (device globals; no allocation) ----------------
__device__ float g_cat[BATCH * 128 * HW];   // 64 MB  : reduce-conv output
__device__ float g_mix[BATCH * 32  * HW];   // 16 MB  : leaky(conv1+embconv)
__device__ float g_wgt[BATCH * 200 * HW];   // 100 MB : conv2 output (involution weights)

__device__ float g_rwT[256 * 128];          // reduce_w transposed [k][oc]
__device__ float g_mixwT[384 * 32];         // combined conv1/embconv transposed [k][oc]
__device__ float g_mixb[32];                // conv1_b + embconv_b
__device__ float g_c2wT[9 * 32 * 200];      // conv2_w transposed [tap][ic][oc]
__device__ float g_owT[128 * 64];           // out_w transposed [c][oc]
__device__ float g_bns[64];                 // BN scale
__device__ float g_bnb[64];                 // BN shift with out_b folded in

// ---------------- prep: weight transposes + BN folding ----------------
__global__ void prep_kernel(const float* __restrict__ reduce_w,
                            const float* __restrict__ conv1_w, const float* __restrict__ conv1_b,
                            const float* __restrict__ embconv_w, const float* __restrict__ embconv_b,
                            const float* __restrict__ conv2_w,
                            const float* __restrict__ out_w, const float* __restrict__ out_b,
                            const float* __restrict__ bn_gamma, const float* __restrict__ bn_beta,
                            const float* __restrict__ bn_mean, const float* __restrict__ bn_var) {
    int tid = blockIdx.x * blockDim.x + threadIdx.x;
    int nt  = gridDim.x * blockDim.x;
    for (int i = tid; i < 256 * 128; i += nt) {
        int k = i >> 7, oc = i & 127;
        g_rwT[i] = reduce_w[oc * 256 + k];
    }
    for (int i = tid; i < 384 * 32; i += nt) {
        int k = i >> 5, oc = i & 31;
        g_mixwT[i] = (k < 128) ? conv1_w[oc * 128 + k] : embconv_w[oc * 256 + (k - 128)];
    }
    for (int i = tid; i < 32; i += nt) g_mixb[i] = conv1_b[i] + embconv_b[i];
    for (int i = tid; i < 9 * 32 * 200; i += nt) {
        int tap = i / 6400;
        int r   = i % 6400;
        int ic  = r / 200;
        int oc  = r % 200;
        g_c2wT[i] = conv2_w[(oc * 32 + ic) * 9 + tap];
    }
    for (int i = tid; i < 128 * 64; i += nt) {
        int c = i >> 6, oc = i & 63;
        g_owT[i] = out_w[oc * 128 + c];
    }
    for (int i = tid; i < 64; i += nt) {
        float s = bn_gamma[i] * rsqrtf(bn_var[i] + 1e-5f);
        g_bns[i] = s;
        g_bnb[i] = bn_beta[i] + (out_b[i] - bn_mean[i]) * s;
    }
}

// ---------------- K1: pixel_shuffle + concat + reduce 1x1 conv ----------------
// GEMM: C[128 oc][64 px] = W[128][256] * X[256][64 px] + b
__global__ void __launch_bounds__(256) k1_cat(const float* __restrict__ hi,
                                              const float* __restrict__ lo,
                                              const float* __restrict__ reduce_b) {
    __shared__ float w_s[32][132];
    __shared__ float x_s[32][68];

    int p0  = blockIdx.x * 64;
    int b   = p0 / HW;
    int rem = p0 % HW;
    int h   = rem / W;
    int w0  = rem % W;

    int t   = threadIdx.x;
    int ty  = t >> 4, tx = t & 15;
    int oc0 = ty * 8, px0 = tx * 4;

    float acc[8][4];
#pragma unroll
    for (int r = 0; r < 8; r++)
#pragma unroll
        for (int c = 0; c < 4; c++) acc[r][c] = 0.f;

    for (int kc = 0; kc < 8; kc++) {
        // weights: 32 x 128
#pragma unroll
        for (int i = 0; i < 16; i++) {
            int idx = t + i * 256;
            int kk = idx >> 7, oc = idx & 127;
            w_s[kk][oc] = g_rwT[(kc * 32 + kk) * 128 + oc];
        }
        // inputs: 32 x 64 (gathered)
#pragma unroll
        for (int i = 0; i < 8; i++) {
            int idx = t + i * 256;
            int kk = idx >> 6, px = idx & 63;
            int k  = kc * 32 + kk;
            int ww = w0 + px;
            float v;
            if (k < 32) {  // pixel shuffle channels
                int ci = k * 4 + ((h & 1) << 1) + (ww & 1);
                v = hi[((b * 128 + ci) * 64 + (h >> 1)) * 64 + (ww >> 1)];
            } else {       // low_level channels
                v = lo[((b * 224 + (k - 32)) * H + h) * W + ww];
            }
            x_s[kk][px] = v;
        }
        __syncthreads();
#pragma unroll
        for (int kk = 0; kk < 32; kk++) {
            float4 a0 = *(const float4*)&w_s[kk][oc0];
            float4 a1 = *(const float4*)&w_s[kk][oc0 + 4];
            float4 bv = *(const float4*)&x_s[kk][px0];
            float av[8] = {a0.x, a0.y, a0.z, a0.w, a1.x, a1.y, a1.z, a1.w};
            float bb[4] = {bv.x, bv.y, bv.z, bv.w};
#pragma unroll
            for (int r = 0; r < 8; r++)
#pragma unroll
                for (int c = 0; c < 4; c++)
                    acc[r][c] = fmaf(av[r], bb[c], acc[r][c]);
        }
        __syncthreads();
    }
#pragma unroll
    for (int r = 0; r < 8; r++) {
        int oc = oc0 + r;
        float bb = reduce_b[oc];
        float4 o;
        o.x = acc[r][0] + bb; o.y = acc[r][1] + bb;
        o.z = acc[r][2] + bb; o.w = acc[r][3] + bb;
        *(float4*)&g_cat[((b * 128 + oc) * H + h) * W + w0 + px0] = o;
    }
}

// ---------------- K2: mix = leaky(conv1(cat) + embconv(emb)) ----------------
// GEMM: [32 oc][128 px], K = 384 (128 cat + 256 emb)
__global__ void __launch_bounds__(256) k2_mix(const float* __restrict__ emb) {
    __shared__ float w_s[32][36];
    __shared__ float x_s[32][132];

    int blk = blockIdx.x;      // b*H + h
    int b = blk / H, h = blk % H;

    int t   = threadIdx.x;
    int ty  = t >> 5, tx = t & 31;
    int oc0 = ty * 4, px0 = tx * 4;

    float acc[4][4];
#pragma unroll
    for (int r = 0; r < 4; r++)
#pragma unroll
        for (int c = 0; c < 4; c++) acc[r][c] = 0.f;

    for (int kc = 0; kc < 12; kc++) {
#pragma unroll
        for (int i = 0; i < 4; i++) {
            int idx = t + i * 256;
            int kk = idx >> 5, oc = idx & 31;
            w_s[kk][oc] = g_mixwT[(kc * 32 + kk) * 32 + oc];
        }
#pragma unroll
        for (int i = 0; i < 16; i++) {
            int idx = t + i * 256;
            int kk = idx >> 7, px = idx & 127;
            int k  = kc * 32 + kk;
            float v = (k < 128)
                ? g_cat[((b * 128 + k) * H + h) * W + px]
                : emb[((b * 256 + (k - 128)) * H + h) * W + px];
            x_s[kk][px] = v;
        }
        __syncthreads();
#pragma unroll
        for (int kk = 0; kk < 32; kk++) {
            float4 a  = *(const float4*)&w_s[kk][oc0];
            float4 bv = *(const float4*)&x_s[kk][px0];
            float av[4] = {a.x, a.y, a.z, a.w};
            float bb[4] = {bv.x, bv.y, bv.z, bv.w};
#pragma unroll
            for (int r = 0; r < 4; r++)
#pragma unroll
                for (int c = 0; c < 4; c++)
                    acc[r][c] = fmaf(av[r], bb[c], acc[r][c]);
        }
        __syncthreads();
    }
#pragma unroll
    for (int r = 0; r < 4; r++) {
        int oc = oc0 + r;
        float bb = g_mixb[oc];
        float4 o;
        float v0 = acc[r][0] + bb, v1 = acc[r][1] + bb, v2 = acc[r][2] + bb, v3 = acc[r][3] + bb;
        o.x = v0 > 0.f ? v0 : 0.01f * v0;
        o.y = v1 > 0.f ? v1 : 0.01f * v1;
        o.z = v2 > 0.f ? v2 : 0.01f * v2;
        o.w = v3 > 0.f ? v3 : 0.01f * v3;
        *(float4*)&g_mix[((b * 32 + oc) * H + h) * W + px0] = o;
    }
}

// ---------------- K3: conv2 3x3, 32 -> 200 (involution weight generator) ----------------
// block: 2 output rows x 32 px, each warp handles 25 consecutive oc, all 200 oc per block
__global__ void __launch_bounds__(256, 2) k3_conv2(const float* __restrict__ c2b) {
    __shared__ float x_s[4][32][36];   // rows h0-1..h0+2, 32 ic, cols w0-1..w0+32 (+pad)
    __shared__ float w_s[32][8][28];   // [ic][oc_group][25 padded to 28]

    int blk = blockIdx.x;              // b*(H/2)*4 + h2*4 + q
    int q   = blk & 3;
    int rest = blk >> 2;
    int h2  = rest & 63;
    int b   = rest >> 6;
    int h0  = h2 * 2;
    int w0  = q * 32;

    int t   = threadIdx.x;
    int px  = t & 31;
    int ocg = t >> 5;                  // 0..7
    int oc0 = ocg * 25;

    float acc[2][25];
#pragma unroll
    for (int r = 0; r < 2; r++)
#pragma unroll
        for (int o = 0; o < 25; o++) acc[r][o] = 0.f;

    // load mix tile once (4 rows)
    for (int i = t; i < 4 * 32 * 36; i += 256) {
        int r   = i / (32 * 36);
        int rr  = i % (32 * 36);
        int ic  = rr / 36;
        int col = rr % 36;
        int hh = h0 - 1 + r;
        int ww = w0 - 1 + col;
        float v = 0.f;
        if (col < 34 && hh >= 0 && hh < H && ww >= 0 && ww < W)
            v = g_mix[((b * 32 + ic) * H + hh) * W + ww];
        x_s[r][ic][col] = v;
    }

    for (int tap = 0; tap < 9; tap++) {
        __syncthreads();  // x_s ready (tap 0); prev-tap compute done before w_s overwrite
        for (int i = t; i < 32 * 8 * 28; i += 256) {
            int kk = i / (8 * 28);
            int rr = i % (8 * 28);
            int og = rr / 28;
            int oo = rr % 28;
            w_s[kk][og][oo] = (oo < 25) ? g_c2wT[(tap * 32 + kk) * 200 + og * 25 + oo] : 0.f;
        }
        __syncthreads();
        int ti = tap / 3, tj = tap % 3;
#pragma unroll
        for (int kk = 0; kk < 32; kk++) {
            float xv0 = x_s[ti][kk][px + tj];
            float xv1 = x_s[ti + 1][kk][px + tj];
            const float* wp = &w_s[kk][ocg][0];
#pragma unroll
            for (int o4 = 0; o4 < 6; o4++) {
                float4 wv = *(const float4*)(wp + o4 * 4);
                acc[0][o4*4+0] = fmaf(wv.x, xv0, acc[0][o4*4+0]);
                acc[0][o4*4+1] = fmaf(wv.y, xv0, acc[0][o4*4+1]);
                acc[0][o4*4+2] = fmaf(wv.z, xv0, acc[0][o4*4+2]);
                acc[0][o4*4+3] = fmaf(wv.w, xv0, acc[0][o4*4+3]);
                acc[1][o4*4+0] = fmaf(wv.x, xv1, acc[1][o4*4+0]);
                acc[1][o4*4+1] = fmaf(wv.y, xv1, acc[1][o4*4+1]);
                acc[1][o4*4+2] = fmaf(wv.z, xv1, acc[1][o4*4+2]);
                acc[1][o4*4+3] = fmaf(wv.w, xv1, acc[1][o4*4+3]);
            }
            float w24 = wp[24];
            acc[0][24] = fmaf(w24, xv0, acc[0][24]);
            acc[1][24] = fmaf(w24, xv1, acc[1][24]);
        }
    }
#pragma unroll
    for (int r = 0; r < 2; r++)
#pragma unroll
        for (int o = 0; o < 25; o++) {
            int oc = oc0 + o;
            g_wgt[((b * 200 + oc) * H + (h0 + r)) * W + w0 + px] = acc[r][o] + c2b[oc];
        }
}

// ---------------- K4: involution + out conv + BN + leaky ----------------
__global__ void __launch_bounds__(256) k4_out(float* __restrict__ out) {
    __shared__ float c_s[16][5][36];   // cat tile for one group
    __shared__ float w_s[25][33];      // involution weights, one group
    __shared__ float o_s[128][33];     // involution output

    int blk = blockIdx.x;              // b*H*4 + h*4 + q
    int q   = blk & 3;
    int h   = (blk >> 2) & 127;
    int b   = blk >> 9;
    int w0  = q * 32;

    int t  = threadIdx.x;
    int px = t & 31;
    int tg = t >> 5;                   // 0..7

    for (int g = 0; g < 8; g++) {
        __syncthreads();
        // cat tile: 16 ch x 5 rows x 36 cols (halo 2)
        for (int i = t; i < 16 * 5 * 36; i += 256) {
            int cc  = i / 180;
            int rr  = (i % 180) / 36;
            int col = i % 36;
            int hh = h - 2 + rr;
            int ww = w0 - 2 + col;
            float v = 0.f;
            if (hh >= 0 && hh < H && ww >= 0 && ww < W)
                v = g_cat[((b * 128 + g * 16 + cc) * H + hh) * W + ww];
            c_s[cc][rr][col] = v;
        }
        // involution weights: 25 taps x 32 px
        for (int i = t; i < 25 * 32; i += 256) {
            int tp = i >> 5;
            int pp = i & 31;
            w_s[tp][pp] = g_wgt[((b * 200 + g * 25 + tp) * H + h) * W + w0 + pp];
        }
        __syncthreads();
        // each thread: 2 channels (tg, tg+8) at its pixel
        float a0 = 0.f, a1 = 0.f;
#pragma unroll
        for (int i = 0; i < 5; i++)
#pragma unroll
            for (int j = 0; j < 5; j++) {
                float wv = w_s[i * 5 + j][px];
                a0 = fmaf(wv, c_s[tg][i][px + j], a0);
                a1 = fmaf(wv, c_s[tg + 8][i][px + j], a1);
            }
        o_s[g * 16 + tg][px]     = a0;
        o_s[g * 16 + tg + 8][px] = a1;
    }
    __syncthreads();

    // out conv (64x128 GEMV per pixel) + BN + leaky
    int oc0 = tg * 8;
    float acc[8];
#pragma unroll
    for (int o = 0; o < 8; o++) acc[o] = 0.f;
#pragma unroll 4
    for (int c = 0; c < 128; c++) {
        float ov = o_s[c][px];
        float4 w0v = *(const float4*)&g_owT[c * 64 + oc0];       // warp-uniform -> bcast LDG
        float4 w1v = *(const float4*)&g_owT[c * 64 + oc0 + 4];
        acc[0] = fmaf(w0v.x, ov, acc[0]);
        acc[1] = fmaf(w0v.y, ov, acc[1]);
        acc[2] = fmaf(w0v.z, ov, acc[2]);
        acc[3] = fmaf(w0v.w, ov, acc[3]);
        acc[4] = fmaf(w1v.x, ov, acc[4]);
        acc[5] = fmaf(w1v.y, ov, acc[5]);
        acc[6] = fmaf(w1v.z, ov, acc[6]);
        acc[7] = fmaf(w1v.w, ov, acc[7]);
    }
#pragma unroll
    for (int o = 0; o < 8; o++) {
        int oc = oc0 + o;
        float y = acc[o] * g_bns[oc] + g_bnb[oc];
        y = y > 0.f ? y : 0.01f * y;
        out[((b * 64 + oc) * H + h) * W + w0 + px] = y;
    }
}

// ---------------- launch ----------------
extern "C" void kernel_launch(void* const* d_in, const int* in_sizes, int n_in,
                              void* d_out, int out_size) {
    const float* hi        = (const float*)d_in[0];
    const float* lo        = (const float*)d_in[1];
    const float* emb       = (const float*)d_in[2];
    const float* reduce_w  = (const float*)d_in[3];
    const float* reduce_b  = (const float*)d_in[4];
    const float* conv1_w   = (const float*)d_in[5];
    const float* conv1_b   = (const float*)d_in[6];
    const float* conv2_w   = (const float*)d_in[7];
    const float* conv2_b   = (const float*)d_in[8];
    const float* embconv_w = (const float*)d_in[9];
    const float* embconv_b = (const float*)d_in[10];
    const float* out_w     = (const float*)d_in[11];
    const float* out_b     = (const float*)d_in[12];
    const float* bn_gamma  = (const float*)d_in[13];
    const float* bn_beta   = (const float*)d_in[14];
    const float* bn_mean   = (const float*)d_in[15];
    const float* bn_var    = (const float*)d_in[16];
    float* out = (float*)d_out;

    prep_kernel<<<128, 256>>>(reduce_w, conv1_w, conv1_b, embconv_w, embconv_b,
                              conv2_w, out_w, out_b, bn_gamma, bn_beta, bn_mean, bn_var);
    k1_cat<<<(BATCH * HW) / 64, 256>>>(hi, lo, reduce_b);      // 2048 blocks
    k2_mix<<<BATCH * H, 256>>>(emb);                           // 1024 blocks
    k3_conv2<<<BATCH * (H / 2) * 4, 256>>>(conv2_b);           // 2048 blocks
    k4_out<<<BATCH * H * 4, 256>>>(out);                       // 4096 blocks
}

// round 8
// speedup vs baseline: 1.4703x; 1.4703x over previous
#include <cuda_runtime.h>

#define BATCH 8
#define H 128
#define W 128
#define HW (H*W)

typedef unsigned long long u64;

__device__ __forceinline__ u64 pack2(float lo, float hi) {
    u64 r; asm("mov.b64 %0, {%1, %2};" : "=l"(r) : "f"(lo), "f"(hi)); return r;
}
__device__ __forceinline__ u64 dup2(float v) {
    u64 r; asm("mov.b64 %0, {%1, %1};" : "=l"(r) : "f"(v)); return r;
}
__device__ __forceinline__ void unpack2(u64 v, float& lo, float& hi) {
    asm("mov.b64 {%0, %1}, %2;" : "=f"(lo), "=f"(hi) : "l"(v));
}
__device__ __forceinline__ void ffma2(u64& d, u64 a, u64 b) {
    asm("fma.rn.f32x2 %0, %1, %2, %0;" : "+l"(d) : "l"(a), "l"(b));
}

// ---------------- scratch (device globals; no allocation) ----------------
__device__ float g_cat[BATCH * 128 * HW];
__device__ float g_mix[BATCH * 32  * HW];
__device__ float g_wgt[BATCH * 200 * HW];

__device__ float g_rwT[256 * 128];            // reduce_w transposed [k][oc]
__device__ float g_mixwT[384 * 32];           // conv1/embconv transposed [k][oc]
__device__ float g_mixb[32];
__device__ float g_c2wP[9 * 32 * 8 * 28];     // conv2_w padded [tap][ic][ocg][28] (oo>=25 -> 0)
__device__ float g_owT[128 * 64];             // out_w transposed [c][oc]
__device__ float g_bns[64];
__device__ float g_bnb[64];

// ---------------- prep ----------------
__global__ void prep_kernel(const float* __restrict__ reduce_w,
                            const float* __restrict__ conv1_w, const float* __restrict__ conv1_b,
                            const float* __restrict__ embconv_w, const float* __restrict__ embconv_b,
                            const float* __restrict__ conv2_w,
                            const float* __restrict__ out_w, const float* __restrict__ out_b,
                            const float* __restrict__ bn_gamma, const float* __restrict__ bn_beta,
                            const float* __restrict__ bn_mean, const float* __restrict__ bn_var) {
    int tid = blockIdx.x * blockDim.x + threadIdx.x;
    int nt  = gridDim.x * blockDim.x;
    for (int i = tid; i < 256 * 128; i += nt) {
        int k = i >> 7, oc = i & 127;
        g_rwT[i] = reduce_w[oc * 256 + k];
    }
    for (int i = tid; i < 384 * 32; i += nt) {
        int k = i >> 5, oc = i & 31;
        g_mixwT[i] = (k < 128) ? conv1_w[oc * 128 + k] : embconv_w[oc * 256 + (k - 128)];
    }
    for (int i = tid; i < 32; i += nt) g_mixb[i] = conv1_b[i] + embconv_b[i];
    for (int i = tid; i < 9 * 32 * 8 * 28; i += nt) {
        int tap = i / 7168;
        int r   = i % 7168;
        int ic  = r / 224;
        int r2  = r % 224;
        int og  = r2 / 28;
        int oo  = r2 % 28;
        float v = 0.f;
        if (oo < 25) v = conv2_w[((og * 25 + oo) * 32 + ic) * 9 + tap];
        g_c2wP[i] = v;
    }
    for (int i = tid; i < 128 * 64; i += nt) {
        int c = i >> 6, oc = i & 63;
        g_owT[i] = out_w[oc * 128 + c];
    }
    for (int i = tid; i < 64; i += nt) {
        float s = bn_gamma[i] * rsqrtf(bn_var[i] + 1e-5f);
        g_bns[i] = s;
        g_bnb[i] = bn_beta[i] + (out_b[i] - bn_mean[i]) * s;
    }
}

// ---------------- K1: pixel_shuffle + concat + reduce 1x1 conv ----------------
__global__ void __launch_bounds__(256) k1_cat(const float* __restrict__ hi,
                                              const float* __restrict__ lo,
                                              const float* __restrict__ reduce_b) {
    __shared__ float w_s[32][132];
    __shared__ float x_s[32][68];

    int p0  = blockIdx.x * 64;
    int b   = p0 / HW;
    int rem = p0 % HW;
    int h   = rem / W;
    int w0  = rem % W;

    int t   = threadIdx.x;
    int ty  = t >> 4, tx = t & 15;
    int oc0 = ty * 8, px0 = tx * 4;

    u64 acc2[4][4];
#pragma unroll
    for (int r = 0; r < 4; r++)
#pragma unroll
        for (int c = 0; c < 4; c++) acc2[r][c] = 0ull;

    for (int kc = 0; kc < 8; kc++) {
#pragma unroll
        for (int i = 0; i < 16; i++) {
            int idx = t + i * 256;
            int kk = idx >> 7, oc = idx & 127;
            w_s[kk][oc] = g_rwT[(kc * 32 + kk) * 128 + oc];
        }
#pragma unroll
        for (int i = 0; i < 8; i++) {
            int idx = t + i * 256;
            int kk = idx >> 6, px = idx & 63;
            int k  = kc * 32 + kk;
            int ww = w0 + px;
            float v;
            if (k < 32) {
                int ci = k * 4 + ((h & 1) << 1) + (ww & 1);
                v = hi[((b * 128 + ci) * 64 + (h >> 1)) * 64 + (ww >> 1)];
            } else {
                v = lo[((b * 224 + (k - 32)) * H + h) * W + ww];
            }
            x_s[kk][px] = v;
        }
        __syncthreads();
#pragma unroll
        for (int kk = 0; kk < 32; kk++) {
            ulonglong2 wa = *(const ulonglong2*)&w_s[kk][oc0];
            ulonglong2 wb = *(const ulonglong2*)&w_s[kk][oc0 + 4];
            float4 bv = *(const float4*)&x_s[kk][px0];
            u64 b0 = dup2(bv.x), b1 = dup2(bv.y), b2 = dup2(bv.z), b3 = dup2(bv.w);
            ffma2(acc2[0][0], wa.x, b0); ffma2(acc2[0][1], wa.x, b1);
            ffma2(acc2[0][2], wa.x, b2); ffma2(acc2[0][3], wa.x, b3);
            ffma2(acc2[1][0], wa.y, b0); ffma2(acc2[1][1], wa.y, b1);
            ffma2(acc2[1][2], wa.y, b2); ffma2(acc2[1][3], wa.y, b3);
            ffma2(acc2[2][0], wb.x, b0); ffma2(acc2[2][1], wb.x, b1);
            ffma2(acc2[2][2], wb.x, b2); ffma2(acc2[2][3], wb.x, b3);
            ffma2(acc2[3][0], wb.y, b0); ffma2(acc2[3][1], wb.y, b1);
            ffma2(acc2[3][2], wb.y, b2); ffma2(acc2[3][3], wb.y, b3);
        }
        __syncthreads();
    }
#pragma unroll
    for (int r2 = 0; r2 < 4; r2++) {
        int ocA = oc0 + 2 * r2, ocB = ocA + 1;
        float bA = reduce_b[ocA], bB = reduce_b[ocB];
        float4 oa, ob;
        unpack2(acc2[r2][0], oa.x, ob.x);
        unpack2(acc2[r2][1], oa.y, ob.y);
        unpack2(acc2[r2][2], oa.z, ob.z);
        unpack2(acc2[r2][3], oa.w, ob.w);
        oa.x += bA; oa.y += bA; oa.z += bA; oa.w += bA;
        ob.x += bB; ob.y += bB; ob.z += bB; ob.w += bB;
        *(float4*)&g_cat[((b * 128 + ocA) * H + h) * W + w0 + px0] = oa;
        *(float4*)&g_cat[((b * 128 + ocB) * H + h) * W + w0 + px0] = ob;
    }
}

// ---------------- K2: mix = leaky(conv1(cat) + embconv(emb)) ----------------
__global__ void __launch_bounds__(256) k2_mix(const float* __restrict__ emb) {
    __shared__ float w_s[32][36];
    __shared__ float x_s[32][132];

    int blk = blockIdx.x;
    int b = blk / H, h = blk % H;

    int t   = threadIdx.x;
    int ty  = t >> 5, tx = t & 31;
    int oc0 = ty * 4, px0 = tx * 4;

    u64 acc2[2][4];
#pragma unroll
    for (int r = 0; r < 2; r++)
#pragma unroll
        for (int c = 0; c < 4; c++) acc2[r][c] = 0ull;

    for (int kc = 0; kc < 12; kc++) {
#pragma unroll
        for (int i = 0; i < 4; i++) {
            int idx = t + i * 256;
            int kk = idx >> 5, oc = idx & 31;
            w_s[kk][oc] = g_mixwT[(kc * 32 + kk) * 32 + oc];
        }
#pragma unroll
        for (int i = 0; i < 16; i++) {
            int idx = t + i * 256;
            int kk = idx >> 7, px = idx & 127;
            int k  = kc * 32 + kk;
            float v = (k < 128)
                ? g_cat[((b * 128 + k) * H + h) * W + px]
                : emb[((b * 256 + (k - 128)) * H + h) * W + px];
            x_s[kk][px] = v;
        }
        __syncthreads();
#pragma unroll
        for (int kk = 0; kk < 32; kk++) {
            ulonglong2 wa = *(const ulonglong2*)&w_s[kk][oc0];
            float4 bv = *(const float4*)&x_s[kk][px0];
            u64 b0 = dup2(bv.x), b1 = dup2(bv.y), b2 = dup2(bv.z), b3 = dup2(bv.w);
            ffma2(acc2[0][0], wa.x, b0); ffma2(acc2[0][1], wa.x, b1);
            ffma2(acc2[0][2], wa.x, b2); ffma2(acc2[0][3], wa.x, b3);
            ffma2(acc2[1][0], wa.y, b0); ffma2(acc2[1][1], wa.y, b1);
            ffma2(acc2[1][2], wa.y, b2); ffma2(acc2[1][3], wa.y, b3);
        }
        __syncthreads();
    }
#pragma unroll
    for (int r2 = 0; r2 < 2; r2++) {
        int ocA = oc0 + 2 * r2, ocB = ocA + 1;
        float bA = g_mixb[ocA], bB = g_mixb[ocB];
        float4 oa, ob;
        unpack2(acc2[r2][0], oa.x, ob.x);
        unpack2(acc2[r2][1], oa.y, ob.y);
        unpack2(acc2[r2][2], oa.z, ob.z);
        unpack2(acc2[r2][3], oa.w, ob.w);
        oa.x += bA; oa.y += bA; oa.z += bA; oa.w += bA;
        ob.x += bB; ob.y += bB; ob.z += bB; ob.w += bB;
        oa.x = oa.x > 0.f ? oa.x : 0.01f * oa.x;
        oa.y = oa.y > 0.f ? oa.y : 0.01f * oa.y;
        oa.z = oa.z > 0.f ? oa.z : 0.01f * oa.z;
        oa.w = oa.w > 0.f ? oa.w : 0.01f * oa.w;
        ob.x = ob.x > 0.f ? ob.x : 0.01f * ob.x;
        ob.y = ob.y > 0.f ? ob.y : 0.01f * ob.y;
        ob.z = ob.z > 0.f ? ob.z : 0.01f * ob.z;
        ob.w = ob.w > 0.f ? ob.w : 0.01f * ob.w;
        *(float4*)&g_mix[((b * 32 + ocA) * H + h) * W + px0] = oa;
        *(float4*)&g_mix[((b * 32 + ocB) * H + h) * W + px0] = ob;
    }
}

// ---------------- K3: conv2 3x3, 32 -> 200 ----------------
__global__ void __launch_bounds__(256, 2) k3_conv2(const float* __restrict__ c2b) {
    __shared__ float x_s[4][32][34];   // 17408 B
    __shared__ float w_s[32][8][28];   // 28672 B   (total 46080 < 48K)

    int blk = blockIdx.x;
    int q   = blk & 3;
    int rest = blk >> 2;
    int h2  = rest & 63;
    int b   = rest >> 6;
    int h0  = h2 * 2;
    int w0  = q * 32;

    int t   = threadIdx.x;
    int px  = t & 31;
    int ocg = t >> 5;
    int oc0 = ocg * 25;

    u64 acc2[2][13];
#pragma unroll
    for (int r = 0; r < 2; r++)
#pragma unroll
        for (int o = 0; o < 13; o++) acc2[r][o] = 0ull;

    // mix halo tile: (ic,col) outer, rows inner — minimal index math
    for (int i = t; i < 32 * 34; i += 256) {
        int ic  = i / 34;
        int col = i % 34;
        int ww = w0 - 1 + col;
        bool okc = (ww >= 0) && (ww < W);
        const float* base = &g_mix[(b * 32 + ic) * HW + ww];
#pragma unroll
        for (int r = 0; r < 4; r++) {
            int hh = h0 - 1 + r;
            float v = 0.f;
            if (okc && hh >= 0 && hh < H) v = base[hh * W];
            x_s[r][ic][col] = v;
        }
    }

    for (int tap = 0; tap < 9; tap++) {
        __syncthreads();
        // flat coalesced copy: 7168 floats = 1792 float4
        {
            const float4* src = (const float4*)(g_c2wP + tap * 7168);
            float4* dst = (float4*)&w_s[0][0][0];
#pragma unroll
            for (int j = 0; j < 7; j++) dst[t + j * 256] = src[t + j * 256];
        }
        __syncthreads();
        int ti = tap / 3, tj = tap % 3;
#pragma unroll
        for (int kk = 0; kk < 32; kk++) {
            u64 x0 = dup2(x_s[ti][kk][px + tj]);
            u64 x1 = dup2(x_s[ti + 1][kk][px + tj]);
            const ulonglong2* wp = (const ulonglong2*)&w_s[kk][ocg][0];
#pragma unroll
            for (int qq = 0; qq < 7; qq++) {
                ulonglong2 wv = wp[qq];
                int p0 = 2 * qq, p1 = 2 * qq + 1;
                if (p0 < 13) { ffma2(acc2[0][p0], wv.x, x0); ffma2(acc2[1][p0], wv.x, x1); }
                if (p1 < 13) { ffma2(acc2[0][p1], wv.y, x0); ffma2(acc2[1][p1], wv.y, x1); }
            }
        }
    }
#pragma unroll
    for (int o2 = 0; o2 < 13; o2++) {
        int ocA = oc0 + 2 * o2;
        float bA = c2b[ocA];
        float bB = (2 * o2 + 1 < 25) ? c2b[ocA + 1] : 0.f;
#pragma unroll
        for (int r = 0; r < 2; r++) {
            float lo, hi;
            unpack2(acc2[r][o2], lo, hi);
            g_wgt[((b * 200 + ocA) * H + (h0 + r)) * W + w0 + px] = lo + bA;
            if (2 * o2 + 1 < 25)
                g_wgt[((b * 200 + ocA + 1) * H + (h0 + r)) * W + w0 + px] = hi + bB;
        }
    }
}

// ---------------- K4: involution + out conv + BN + leaky ----------------
__global__ void __launch_bounds__(256) k4_out(float* __restrict__ out) {
    __shared__ float c_s[16][5][36];
    __shared__ float w_s[25][33];
    __shared__ float o_s[128][33];

    int blk = blockIdx.x;
    int q   = blk & 3;
    int h   = (blk >> 2) & 127;
    int b   = blk >> 9;
    int w0  = q * 32;

    int t  = threadIdx.x;
    int px = t & 31;
    int tg = t >> 5;

    for (int g = 0; g < 8; g++) {
        __syncthreads();
        // cat tile: (cc,col) outer, rows inner
        for (int i = t; i < 16 * 36; i += 256) {
            int cc  = i / 36;
            int col = i % 36;
            int ww = w0 - 2 + col;
            bool okc = (ww >= 0) && (ww < W);
            const float* base = &g_cat[(b * 128 + g * 16 + cc) * HW + ww];
#pragma unroll
            for (int rr = 0; rr < 5; rr++) {
                int hh = h - 2 + rr;
                float v = 0.f;
                if (okc && hh >= 0 && hh < H) v = base[hh * W];
                c_s[cc][rr][col] = v;
            }
        }
        // involution weights: 25 taps x 32 px
        for (int i = t; i < 25 * 32; i += 256) {
            int tp = i >> 5;
            int pp = i & 31;
            w_s[tp][pp] = g_wgt[((b * 200 + g * 25 + tp) * H + h) * W + w0 + pp];
        }
        __syncthreads();
        float a0 = 0.f, a1 = 0.f;
#pragma unroll
        for (int i = 0; i < 5; i++)
#pragma unroll
            for (int j = 0; j < 5; j++) {
                float wv = w_s[i * 5 + j][px];
                a0 = fmaf(wv, c_s[tg][i][px + j], a0);
                a1 = fmaf(wv, c_s[tg + 8][i][px + j], a1);
            }
        o_s[g * 16 + tg][px]     = a0;
        o_s[g * 16 + tg + 8][px] = a1;
    }
    __syncthreads();

    // out conv GEMV (packed f32x2) + BN + leaky
    int oc0 = tg * 8;
    u64 acc2[4] = {0ull, 0ull, 0ull, 0ull};
#pragma unroll 4
    for (int c = 0; c < 128; c++) {
        u64 od = dup2(o_s[c][px]);
        ulonglong2 wa = *(const ulonglong2*)&g_owT[c * 64 + oc0];
        ulonglong2 wb = *(const ulonglong2*)&g_owT[c * 64 + oc0 + 4];
        ffma2(acc2[0], wa.x, od);
        ffma2(acc2[1], wa.y, od);
        ffma2(acc2[2], wb.x, od);
        ffma2(acc2[3], wb.y, od);
    }
#pragma unroll
    for (int i = 0; i < 4; i++) {
        float lo, hi;
        unpack2(acc2[i], lo, hi);
        int ocA = oc0 + 2 * i, ocB = ocA + 1;
        float yA = lo * g_bns[ocA] + g_bnb[ocA];
        float yB = hi * g_bns[ocB] + g_bnb[ocB];
        yA = yA > 0.f ? yA : 0.01f * yA;
        yB = yB > 0.f ? yB : 0.01f * yB;
        out[((b * 64 + ocA) * H + h) * W + w0 + px] = yA;
        out[((b * 64 + ocB) * H + h) * W + w0 + px] = yB;
    }
}

// ---------------- launch ----------------
extern "C" void kernel_launch(void* const* d_in, const int* in_sizes, int n_in,
                              void* d_out, int out_size) {
    const float* hi        = (const float*)d_in[0];
    const float* lo        = (const float*)d_in[1];
    const float* emb       = (const float*)d_in[2];
    const float* reduce_w  = (const float*)d_in[3];
    const float* reduce_b  = (const float*)d_in[4];
    const float* conv1_w   = (const float*)d_in[5];
    const float* conv1_b   = (const float*)d_in[6];
    const float* conv2_w   = (const float*)d_in[7];
    const float* conv2_b   = (const float*)d_in[8];
    const float* embconv_w = (const float*)d_in[9];
    const float* embconv_b = (const float*)d_in[10];
    const float* out_w     = (const float*)d_in[11];
    const float* out_b     = (const float*)d_in[12];
    const float* bn_gamma  = (const float*)d_in[13];
    const float* bn_beta   = (const float*)d_in[14];
    const float* bn_mean   = (const float*)d_in[15];
    const float* bn_var    = (const float*)d_in[16];
    float* out = (float*)d_out;

    prep_kernel<<<128, 256>>>(reduce_w, conv1_w, conv1_b, embconv_w, embconv_b,
                              conv2_w, out_w, out_b, bn_gamma, bn_beta, bn_mean, bn_var);
    k1_cat<<<(BATCH * HW) / 64, 256>>>(hi, lo, reduce_b);
    k2_mix<<<BATCH * H, 256>>>(emb);
    k3_conv2<<<BATCH * (H / 2) * 4, 256>>>(conv2_b);
    k4_out<<<BATCH * H * 4, 256>>>(out);
}